// round 5
// baseline (speedup 1.0000x reference)
#include <cuda_runtime.h>
#include <cstddef>

// Problem shape (fixed by the dataset):
//   emissions (B,S,T) f32, tags (B,S) staged as int32, mask (B,S) f32,
//   transitions (T,T) f32, start_transitions (T) f32, end_transitions (T) f32
//   output: scalar f32 = sum_b (partition_b - score_b)
#define B_SZ 512
#define S_SZ 1024
#define T_SZ 32
#define FULL 0xFFFFFFFFu

// per-batch (partition - score), filled by crf_kernel, summed by crf_reduce
__device__ float g_res[B_SZ];

__global__ void __launch_bounds__(128) crf_kernel(
    const float* __restrict__ em,        // (B,S,T)
    const int*   __restrict__ tags,      // (B,S)  int32 (harness stages int64 -> int32)
    const float* __restrict__ mask,      // (B,S)
    const float* __restrict__ trans,     // (T,T)
    const float* __restrict__ startT,    // (T)
    const float* __restrict__ endT)      // (T)
{
    const int warp = (blockIdx.x * blockDim.x + threadIdx.x) >> 5;
    const int lane = threadIdx.x & 31;
    const int b = warp;
    if (b >= B_SZ) return;

    // Lane j holds column j of exp(transitions): et[i] = exp(trans[i][j]).
    // For fixed i, lanes read 128B contiguous -> coalesced.
    float et[T_SZ];
#pragma unroll
    for (int i = 0; i < T_SZ; ++i)
        et[i] = __expf(__ldg(trans + i * T_SZ + lane));

    const float* emb = em + (size_t)b * S_SZ * T_SZ;
    const float* mb  = mask + (size_t)b * S_SZ;

    // alpha at s=0 (absolute log-domain value; |alpha| stays < ~4000 -> fp32 OK)
    float alpha = __ldg(startT + lane) + __ldg(emb + lane);

    // Lag-2 shift pipeline: d used at step s equals alpha^{s-2}[0], so the
    // SHFL that produced it was issued a full step earlier (latency hidden).
    float d0 = __shfl_sync(FULL, alpha, 0);
    float d1 = d0;

    // Prefetch ring (depth 8) for emissions + mask: hides DRAM latency
    float ebuf[8], mbuf[8];
#pragma unroll
    for (int k = 0; k < 8; ++k) {
        int s = 1 + k;
        ebuf[k] = (s < S_SZ) ? __ldg(emb + s * T_SZ + lane) : 0.0f;
        mbuf[k] = (s < S_SZ) ? __ldg(mb + s) : 0.0f;
    }

#pragma unroll 8
    for (int s = 1; s < S_SZ; ++s) {
        const int slot = (s - 1) & 7;
        const float e = ebuf[slot];
        const float m = mbuf[slot];
        const int sp = s + 8;
        if (sp < S_SZ) {
            ebuf[slot] = __ldg(emb + sp * T_SZ + lane);
            mbuf[slot] = __ldg(mb + sp);
        }

        const float d = d1;      // alpha^{s-2}[0]
        d1 = d0;

        // next_alpha[j] = d + log( sum_i exp(alpha_i - d) * expT[i][j] ) + e_j
        const float p = __expf(alpha - d);

        float a0 = 0.f, a1 = 0.f, a2 = 0.f, a3 = 0.f;
#pragma unroll
        for (int i = 0; i < T_SZ; i += 4) {
            a0 = fmaf(__shfl_sync(FULL, p, i + 0), et[i + 0], a0);
            a1 = fmaf(__shfl_sync(FULL, p, i + 1), et[i + 1], a1);
            a2 = fmaf(__shfl_sync(FULL, p, i + 2), et[i + 2], a2);
            a3 = fmaf(__shfl_sync(FULL, p, i + 3), et[i + 3], a3);
        }
        const float dot = (a0 + a1) + (a2 + a3);

        const float na = d + __logf(dot) + e;
        // exact when m is 0 or 1 (matches reference blend)
        alpha = na * m + alpha * (1.0f - m);

        d0 = __shfl_sync(FULL, alpha, 0);   // off critical path (used at s+2)
    }

    // ---- partition_b = logsumexp_j(alpha_j + endT[j]) (exact max shift) ----
    float v = alpha + __ldg(endT + lane);
    float mx = v;
#pragma unroll
    for (int o = 16; o > 0; o >>= 1)
        mx = fmaxf(mx, __shfl_xor_sync(FULL, mx, o));
    float ex = __expf(v - mx);
#pragma unroll
    for (int o = 16; o > 0; o >>= 1)
        ex += __shfl_xor_sync(FULL, ex, o);
    const float part = mx + __logf(ex);

    // ---- score_b: lanes stride over sequence positions ----
    const int* tb = tags + (size_t)b * S_SZ;
    float sacc = 0.f, msum = 0.f;
#pragma unroll 4
    for (int s = lane; s < S_SZ; s += 32) {
        const float mm = __ldg(mb + s);
        msum += mm;
        if (s == 0) {
            const int t0 = __ldg(tb) & (T_SZ - 1);          // defensive mask, no-op for valid tags
            sacc += __ldg(startT + t0) + __ldg(emb + t0);
        } else {
            const int tc = __ldg(tb + s)     & (T_SZ - 1);
            const int tp = __ldg(tb + s - 1) & (T_SZ - 1);
            sacc += (__ldg(emb + s * T_SZ + tc) + __ldg(trans + tp * T_SZ + tc)) * mm;
        }
    }
#pragma unroll
    for (int o = 16; o > 0; o >>= 1) {
        sacc += __shfl_xor_sync(FULL, sacc, o);
        msum += __shfl_xor_sync(FULL, msum, o);
    }

    if (lane == 0) {
        int last = (int)msum - 1;
        last = last < 0 ? 0 : (last >= S_SZ ? S_SZ - 1 : last);   // defensive clamp
        const int tl = __ldg(tb + last) & (T_SZ - 1);
        const float score = sacc + __ldg(endT + tl);
        g_res[b] = part - score;
    }
}

// Deterministic tree reduction of 512 per-batch values -> scalar
__global__ void crf_reduce(float* __restrict__ out)
{
    __shared__ float sh[256];
    const int t = threadIdx.x;
    sh[t] = g_res[t] + g_res[t + 256];
    __syncthreads();
#pragma unroll
    for (int st = 128; st > 0; st >>= 1) {
        if (t < st) sh[t] += sh[t + st];
        __syncthreads();
    }
    if (t == 0) out[0] = sh[0];
}

extern "C" void kernel_launch(void* const* d_in, const int* in_sizes, int n_in,
                              void* d_out, int out_size)
{
    const float* em     = (const float*)d_in[0];
    const int*   tags   = (const int*)d_in[1];     // int64 staged as int32
    const float* mask   = (const float*)d_in[2];
    const float* trans  = (const float*)d_in[3];
    const float* startT = (const float*)d_in[4];
    const float* endT   = (const float*)d_in[5];
    float* out = (float*)d_out;

    (void)in_sizes; (void)n_in; (void)out_size;

    // 128 blocks x 128 threads = 512 warps = one warp per batch
    crf_kernel<<<B_SZ / 4, 128>>>(em, tags, mask, trans, startT, endT);
    crf_reduce<<<1, 256>>>(out);
}

// round 6
// speedup vs baseline: 1.7839x; 1.7839x over previous
#include <cuda_runtime.h>
#include <cstddef>

// CRF NLL: emissions (B,S,T) f32, tags (B,S) int32-staged, mask (B,S) f32,
// transitions (T,T) f32, start_transitions (T) f32, end_transitions (T) f32
// out: scalar f32 = sum_b (partition_b - score_b)
#define B_SZ 512
#define S_SZ 1024
#define T_SZ 32
#define FULL 0xFFFFFFFFu
#define LN2F 0.69314718055994530942f

__device__ float    g_res[B_SZ];
__device__ unsigned g_cnt;   // zero-init; reset by last block each launch

__global__ void __launch_bounds__(128) crf_kernel(
    const float* __restrict__ em,
    const int*   __restrict__ tags,
    const float* __restrict__ mask,
    const float* __restrict__ trans,
    const float* __restrict__ startT,
    const float* __restrict__ endT,
    float*       __restrict__ out)
{
    const int widx = threadIdx.x >> 5;
    const int lane = threadIdx.x & 31;
    const int b    = blockIdx.x * 4 + widx;   // grid=128 blocks x 4 warps = 512

    // ping-pong broadcast buffers: [parity][warp][lane]
    __shared__ __align__(16) float sw[2][4][32];
    __shared__ float red[128];
    __shared__ unsigned s_ticket;

    // lane j holds column j of exp(transitions)
    float et[T_SZ];
#pragma unroll
    for (int i = 0; i < T_SZ; ++i)
        et[i] = __expf(__ldg(trans + i * T_SZ + lane));

    const float* emb = em   + (size_t)b * S_SZ * T_SZ;
    const float* mb  = mask + (size_t)b * S_SZ;

    // exp-domain state: alpha_j = log(w_j) + E*ln2   (E warp-uniform)
    float w = __expf(__ldg(startT + lane) + __ldg(emb + lane));
    int   E = 0;

    sw[0][widx][lane] = w;   // prime buffer 0 (read by step 1)

    // scale pipeline (lag-2): sc_a/k_a applied now, sc_b/k_b in flight
    float mx = w;
#pragma unroll
    for (int o = 16; o > 0; o >>= 1) mx = fmaxf(mx, __shfl_xor_sync(FULL, mx, o));
    int   ei   = (int)((__float_as_uint(mx) >> 23) & 0xFF);
    float sc_b = __uint_as_float((unsigned)(254 - ei) << 23);   // 2^(127-ei)
    int   k_b  = ei - 127;
    float sc_a = 1.0f;
    int   k_a  = 0;

    // prefetch ring (depth 8): exp(emission) + mask.  EX2 happens here,
    // 8 steps ahead of use -> off the critical path.
    float eebuf[8], mbuf[8];
#pragma unroll
    for (int k = 0; k < 8; ++k) {
        eebuf[k] = __expf(__ldg(emb + (1 + k) * T_SZ + lane));
        mbuf[k]  = __ldg(mb + 1 + k);
    }

    const float4* rd0 = (const float4*)(sw[0][widx]);
    const float4* rd1 = (const float4*)(sw[1][widx]);

    // main loop split so every unrolled body has compile-time ring slot/parity
#pragma unroll 8
    for (int s = 1; s < 1017; ++s) {        // 1016 iters = 127 * 8
        const int   slot = (s - 1) & 7;
        const float ee   = eebuf[slot];
        const float m    = mbuf[slot];
        const int   sp   = s + 8;
        if (sp < S_SZ) {
            eebuf[slot] = __expf(__ldg(emb + sp * T_SZ + lane));
            mbuf[slot]  = __ldg(mb + sp);
        }

        __syncwarp();
        const float4* rp = ((s - 1) & 1) ? rd1 : rd0;
        float acc[8];
#pragma unroll
        for (int c = 0; c < 8; ++c) {
            const float4 W = rp[c];
            float a;
            a = W.x * et[4 * c + 0];
            a = fmaf(W.y, et[4 * c + 1], a);
            a = fmaf(W.z, et[4 * c + 2], a);
            a = fmaf(W.w, et[4 * c + 3], a);
            acc[c] = a;
        }
        const float dot = ((acc[0] + acc[1]) + (acc[2] + acc[3]))
                        + ((acc[4] + acc[5]) + (acc[6] + acc[7]));

        const float wn = dot * ee;
        w = fmaf(m, wn - w, w);     // mask blend (m is 0 or 1)
        w *= sc_a;  E += k_a;       // apply lag-2 renormalization (exact 2^-k)
        sc_a = sc_b;  k_a = k_b;

        sw[s & 1][widx][lane] = w;

        // off-path: next scale from current max
        float mx2 = w;
#pragma unroll
        for (int o = 16; o > 0; o >>= 1) mx2 = fmaxf(mx2, __shfl_xor_sync(FULL, mx2, o));
        const int e2 = (int)((__float_as_uint(mx2) >> 23) & 0xFF);
        sc_b = __uint_as_float((unsigned)(254 - e2) << 23);
        k_b  = e2 - 127;
    }
    // tail: 7 steps, fully unrolled (compile-time slots/parity)
#pragma unroll
    for (int s = 1017; s < S_SZ; ++s) {
        const int   slot = (s - 1) & 7;
        const float ee   = eebuf[slot];
        const float m    = mbuf[slot];

        __syncwarp();
        const float4* rp = ((s - 1) & 1) ? rd1 : rd0;
        float acc[8];
#pragma unroll
        for (int c = 0; c < 8; ++c) {
            const float4 W = rp[c];
            float a;
            a = W.x * et[4 * c + 0];
            a = fmaf(W.y, et[4 * c + 1], a);
            a = fmaf(W.z, et[4 * c + 2], a);
            a = fmaf(W.w, et[4 * c + 3], a);
            acc[c] = a;
        }
        const float dot = ((acc[0] + acc[1]) + (acc[2] + acc[3]))
                        + ((acc[4] + acc[5]) + (acc[6] + acc[7]));

        const float wn = dot * ee;
        w = fmaf(m, wn - w, w);
        w *= sc_a;  E += k_a;
        sc_a = sc_b;  k_a = k_b;

        sw[s & 1][widx][lane] = w;

        float mx2 = w;
#pragma unroll
        for (int o = 16; o > 0; o >>= 1) mx2 = fmaxf(mx2, __shfl_xor_sync(FULL, mx2, o));
        const int e2 = (int)((__float_as_uint(mx2) >> 23) & 0xFF);
        sc_b = __uint_as_float((unsigned)(254 - e2) << 23);
        k_b  = e2 - 127;
    }

    // ---- partition_b = E*ln2 + log( sum_j w_j * exp(endT_j) ) ----
    float v = w * __expf(__ldg(endT + lane));
#pragma unroll
    for (int o = 16; o > 0; o >>= 1)
        v += __shfl_xor_sync(FULL, v, o);
    const float part = fmaf((float)E, LN2F, __logf(v));

    // ---- score_b: lanes stride over positions ----
    const int* tb = tags + (size_t)b * S_SZ;
    float sacc = 0.f, msum = 0.f;
#pragma unroll 4
    for (int s = lane; s < S_SZ; s += 32) {
        const float mm = __ldg(mb + s);
        msum += mm;
        if (s == 0) {
            const int t0 = __ldg(tb) & (T_SZ - 1);
            sacc += __ldg(startT + t0) + __ldg(emb + t0);
        } else {
            const int tc = __ldg(tb + s)     & (T_SZ - 1);
            const int tp = __ldg(tb + s - 1) & (T_SZ - 1);
            sacc += (__ldg(emb + s * T_SZ + tc) + __ldg(trans + tp * T_SZ + tc)) * mm;
        }
    }
#pragma unroll
    for (int o = 16; o > 0; o >>= 1) {
        sacc += __shfl_xor_sync(FULL, sacc, o);
        msum += __shfl_xor_sync(FULL, msum, o);
    }

    if (lane == 0) {
        int last = (int)msum - 1;
        last = last < 0 ? 0 : (last >= S_SZ ? S_SZ - 1 : last);
        const int tl = __ldg(tb + last) & (T_SZ - 1);
        g_res[b] = part - (sacc + __ldg(endT + tl));
    }

    // ---- fused final reduction: last block sums all 512 results ----
    __syncthreads();
    __threadfence();
    if (threadIdx.x == 0)
        s_ticket = atomicAdd(&g_cnt, 1u);
    __syncthreads();

    if (s_ticket == gridDim.x - 1) {
        const int t = threadIdx.x;
        red[t] = g_res[t] + g_res[t + 128] + g_res[t + 256] + g_res[t + 384];
        __syncthreads();
#pragma unroll
        for (int st = 64; st > 0; st >>= 1) {
            if (t < st) red[t] += red[t + st];
            __syncthreads();
        }
        if (t == 0) { out[0] = red[0]; g_cnt = 0; }
    }
}

extern "C" void kernel_launch(void* const* d_in, const int* in_sizes, int n_in,
                              void* d_out, int out_size)
{
    const float* em     = (const float*)d_in[0];
    const int*   tags   = (const int*)d_in[1];
    const float* mask   = (const float*)d_in[2];
    const float* trans  = (const float*)d_in[3];
    const float* startT = (const float*)d_in[4];
    const float* endT   = (const float*)d_in[5];
    float* out = (float*)d_out;

    (void)in_sizes; (void)n_in; (void)out_size;

    crf_kernel<<<B_SZ / 4, 128>>>(em, tags, mask, trans, startT, endT, out);
}